// round 15
// baseline (speedup 1.0000x reference)
#include <cuda_runtime.h>
#include <cuda_fp16.h>
#include <cstdint>

#define TT 512
#define BB 64
#define HH 512
#define GG 2048
#define TB (TT*BB)

__device__ __align__(16) __half g_x16[2][(size_t)TB * 1024];   // layer activations (fp16)
__device__ __align__(16) float  g_xf[(size_t)TB * 1024];       // final-layer fp32 output
__device__ __align__(16) __half g_gx16[2][(size_t)TB * 2048];  // gate-interleaved [r][j][4]
__device__ __align__(16) __half g_w16[2 * 2048 * 1024];        // per-layer W_ih fp16
__device__ __align__(16) __half g_h16[2][2][BB * HH];
__device__ __align__(16) float  g_hout[2][BB * HH];
__device__ __align__(16) float  g_c[2][BB * HH];
__device__ int g_len[BB];
__device__ int g_nact[TT];
__device__ unsigned g_bar2[2][32];

__device__ __forceinline__ float sigm(float x) { return 1.0f / (1.0f + expf(-x)); }
__device__ __forceinline__ void cp_async16(uint32_t saddr, const void* gaddr) {
    asm volatile("cp.async.cg.shared.global [%0], [%1], 16;\n" :: "r"(saddr), "l"(gaddr));
}
__device__ __forceinline__ void ldsm_x4(uint32_t& r0, uint32_t& r1,
                                        uint32_t& r2, uint32_t& r3, uint32_t saddr) {
    asm volatile("ldmatrix.sync.aligned.m8n8.x4.shared.b16 {%0,%1,%2,%3}, [%4];"
                 : "=r"(r0), "=r"(r1), "=r"(r2), "=r"(r3) : "r"(saddr));
}
__device__ __forceinline__ void mma_f16(float4& d, const uint32_t* a, const uint32_t* b) {
    asm volatile(
        "mma.sync.aligned.m16n8k16.row.col.f32.f16.f16.f32 "
        "{%0,%1,%2,%3}, {%4,%5,%6,%7}, {%8,%9}, {%0,%1,%2,%3};\n"
        : "+f"(d.x), "+f"(d.y), "+f"(d.z), "+f"(d.w)
        : "r"(a[0]), "r"(a[1]), "r"(a[2]), "r"(a[3]), "r"(b[0]), "r"(b[1]));
}
__device__ __forceinline__ uint32_t h2u(__half2 h) { return *reinterpret_cast<uint32_t*>(&h); }

__global__ void k_len(const int* __restrict__ pack_idx, int NP) {
    __shared__ int cnt[BB];
    int tid = threadIdx.x;
    if (tid < BB) cnt[tid] = 0;
    __syncthreads();
    for (int i = tid; i < NP; i += blockDim.x)
        atomicAdd(&cnt[pack_idx[i] & (BB - 1)], 1);
    __syncthreads();
    if (tid < BB) g_len[tid] = cnt[tid];
    if (tid < TT) {
        int t = tid, na = 0;
#pragma unroll 8
        for (int b = 0; b < BB; b++) na += (cnt[b] > t) ? 1 : 0;
        g_nact[t] = na;
    }
}

__global__ void k_wcvt(const float* __restrict__ W, int n4) {
    int i = blockIdx.x * blockDim.x + threadIdx.x;
    if (i < n4) {
        float4 v = *(const float4*)(W + (size_t)i * 4);
        uint2 h = { h2u(__floats2half2_rn(v.x, v.y)), h2u(__floats2half2_rn(v.z, v.w)) };
        *(uint2*)(g_w16 + (size_t)i * 4) = h;
    }
}

__global__ void k_scatter(const float* __restrict__ data, const int* __restrict__ pack_idx, int total) {
    int e = blockIdx.x * blockDim.x + threadIdx.x;
    if (e < total) {
        int i = e >> 9, col = e & 511;
        g_x16[0][(size_t)pack_idx[i] * 512 + col] = __float2half_rn(data[e]);
    }
}

__global__ void k_gather(float* __restrict__ out, const int* __restrict__ pack_idx, int total) {
    int e = blockIdx.x * blockDim.x + threadIdx.x;
    if (e < total) {
        int i = e >> 10, col = e & 1023;
        out[e] = g_xf[(size_t)pack_idx[i] * 1024 + col];
    }
}

__global__ void k_init(const float* __restrict__ h0, const float* __restrict__ c0, int l) {
    int idx = blockIdx.x * blockDim.x + threadIdx.x;
    if (idx < 2) g_bar2[idx][0] = 0u;
    int dir = idx >> 15, rem = idx & 32767;
    size_t src = (size_t)(2 * l + dir) * 32768 + rem;
    float h = h0[src];
    g_h16[0][dir][rem] = __float2half_rn(h);
    g_hout[dir][rem]   = h;
    g_c[dir][rem]      = c0[src];
}

__global__ void k_save(float* __restrict__ out, int NP, int l) {
    int idx = blockIdx.x * blockDim.x + threadIdx.x;
    int dir = idx >> 15, rem = idx & 32767;
    size_t OH = (size_t)NP * 1024;
    size_t off = (size_t)(2 * l + dir) * 32768 + rem;
    out[OH + off]             = g_hout[dir][rem];
    out[OH + 6 * 32768 + off] = g_c[dir][rem];
}

// ---------------------------------------------------------------------------
// Input GEMM, cp.async 3-stage pipeline, all-fp16 operands.
// grid = (32 n-tiles, 256 m-tiles)  [n fast -> X reused 32x from L2]
// Writes gx gate-interleaved fp16: g_gx16[dir][row*2048 + j*4 + quad].
// ---------------------------------------------------------------------------
__global__ __launch_bounds__(256)
void k_gemm_gx(int xsel, int ldx, int K, int dir, const float* __restrict__ bias) {
    const __half* X = g_x16[xsel];
    const __half* W = g_w16 + (size_t)dir * 2048 * K;
    __half* og = g_gx16[dir];

    __shared__ __align__(16) __half Xs[3][128 * 40];
    __shared__ __align__(16) __half Wsm[3][64 * 40];
    uint32_t Xs_s = (uint32_t)__cvta_generic_to_shared(&Xs[0][0]);
    uint32_t Ws_s = (uint32_t)__cvta_generic_to_shared(&Wsm[0][0]);

    int tid = threadIdx.x, lane = tid & 31, warp = tid >> 5;
    int wm = warp & 3, wn = warp >> 2;
    int gid = lane >> 2, tig = lane & 3;
    int sel = lane >> 3, rowin = lane & 7;
    int n0 = blockIdx.x * 64, m0 = blockIdx.y * 128;
    int NC = K / 32;

    float4 acc[2][4];
#pragma unroll
    for (int mt = 0; mt < 2; mt++)
#pragma unroll
        for (int nt = 0; nt < 4; nt++) acc[mt][nt] = make_float4(0.f, 0.f, 0.f, 0.f);

#define GPREF(kc, st)                                                          \
    {                                                                          \
        int k0 = (kc) * 32;                                                    \
        uint32_t xb = Xs_s + (uint32_t)(st) * 10240;                           \
        _Pragma("unroll")                                                      \
        for (int i = 0; i < 2; i++) {                                          \
            int idx = i * 256 + tid, r = idx >> 2, c = idx & 3;                \
            cp_async16(xb + (uint32_t)(r * 80 + c * 16),                       \
                       X + (size_t)(m0 + r) * ldx + k0 + c * 8);               \
        }                                                                      \
        uint32_t wb = Ws_s + (uint32_t)(st) * 5120;                            \
        { int r = tid >> 2, c = tid & 3;                                       \
          cp_async16(wb + (uint32_t)(r * 80 + c * 16),                         \
                     W + (size_t)(n0 + r) * K + k0 + c * 8); }                 \
        asm volatile("cp.async.commit_group;\n" ::: "memory");                 \
    }

    GPREF(0, 0)
    GPREF(1, 1)

    for (int kc = 0; kc < NC; kc++) {
        asm volatile("cp.async.wait_group 1;\n" ::: "memory");
        __syncthreads();
        if (kc + 2 < NC) GPREF(kc + 2, (kc + 2) % 3)
        uint32_t xb = Xs_s + (uint32_t)(kc % 3) * 10240;
        uint32_t wb = Ws_s + (uint32_t)(kc % 3) * 5120;
#pragma unroll
        for (int kk = 0; kk < 2; kk++) {
            uint32_t a[2][4], b[4][2];
#pragma unroll
            for (int mt = 0; mt < 2; mt++) {
                int m = wm * 32 + mt * 16 + (sel & 1) * 8 + rowin;
                int c8 = kk * 2 + (sel >> 1);
                ldsm_x4(a[mt][0], a[mt][1], a[mt][2], a[mt][3],
                        xb + (uint32_t)(m * 80 + c8 * 16));
            }
#pragma unroll
            for (int p = 0; p < 2; p++) {
                int quad = lane >> 3;
                int n = wn * 32 + p * 16 + (quad >> 1) * 8 + rowin;
                int c8 = kk * 2 + (quad & 1);
                ldsm_x4(b[p * 2][0], b[p * 2][1], b[p * 2 + 1][0], b[p * 2 + 1][1],
                        wb + (uint32_t)(n * 80 + c8 * 16));
            }
#pragma unroll
            for (int mt = 0; mt < 2; mt++)
#pragma unroll
                for (int nt = 0; nt < 4; nt++) mma_f16(acc[mt][nt], a[mt], b[nt]);
        }
    }
#undef GPREF

#pragma unroll
    for (int mt = 0; mt < 2; mt++)
#pragma unroll
        for (int nt = 0; nt < 4; nt++) {
            int row = m0 + wm * 32 + mt * 16 + gid;
            int col = n0 + wn * 32 + nt * 8 + tig * 2;
            int quad = col >> 9, j = col & 511;
            float bx = bias[col], by = bias[col + 1];
            size_t base = (size_t)row * 2048 + j * 4 + quad;
            og[base]     = __float2half_rn(acc[mt][nt].x + bx);
            og[base + 4] = __float2half_rn(acc[mt][nt].y + by);
            base += (size_t)8 * 2048;
            og[base]     = __float2half_rn(acc[mt][nt].z + bx);
            og[base + 4] = __float2half_rn(acc[mt][nt].w + by);
        }
}

// ---------------------------------------------------------------------------
// Persistent scan (fp16 split-K). Changes vs R13: gx16 interleaved prefetch
// moved AFTER barrier arrive; active-tile bounding via g_nact.
// ---------------------------------------------------------------------------
#define REGF 2560
#define SCAN_SMEM (8 * REGF * 4)

__global__ __launch_bounds__(256, 1)
void k_scan(const float* __restrict__ Whh0, const float* __restrict__ Whh1,
            int xoutsel, int final) {
    extern __shared__ float s[];
    int bid = blockIdx.x;
    int dir = bid >> 6;
    int j0 = (bid & 63) * 8;
    const float* Whh = dir ? Whh1 : Whh0;
    const __half* gx = g_gx16[dir];
    __half* xo16 = g_x16[xoutsel];

    int tid = threadIdx.x, lane = tid & 31, warp = tid >> 5;
    int gid = lane >> 2, tig = lane & 3;
    int sel = lane >> 3, rowin = lane & 7;
    float* myR = s + warp * REGF;
    uint32_t myR_s = (uint32_t)__cvta_generic_to_shared(myR);

    int hi = sel >> 1;
    uint32_t mbase[4];
    int m7[4];
#pragma unroll
    for (int mt = 0; mt < 4; mt++) {
        int m = mt * 16 + (sel & 1) * 8 + rowin;
        mbase[mt] = myR_s + (uint32_t)(m * 128);
        m7[mt] = m & 7;
    }

    uint32_t wr[4][4][2];
#pragma unroll
    for (int nt = 0; nt < 4; nt++) {
        const float* wrow = Whh + (size_t)(nt * 512 + j0 + gid) * HH + warp * 64;
#pragma unroll
        for (int kk = 0; kk < 4; kk++) {
            const float* wp = wrow + kk * 16;
            wr[nt][kk][0] = h2u(__floats2half2_rn(__ldg(wp + 2 * tig), __ldg(wp + 2 * tig + 1)));
            wr[nt][kk][1] = h2u(__floats2half2_rn(__ldg(wp + 2 * tig + 8), __ldg(wp + 2 * tig + 9)));
        }
    }

    int cb[2], cjj[2], clb[2], cbj[2];
    float creg[2];
    uint2 gxp[2];
#pragma unroll
    for (int it = 0; it < 2; it++) {
        int cell = it * 256 + tid;
        cb[it] = cell >> 3; cjj[it] = cell & 7;
        clb[it] = g_len[cb[it]];
        cbj[it] = cb[it] * HH + j0 + cjj[it];
        creg[it] = g_c[dir][cbj[it]];
    }

#define PREFETCH_GX(t)                                                        \
    {                                                                         \
        _Pragma("unroll")                                                     \
        for (int it = 0; it < 2; it++) {                                      \
            if ((t) < clb[it]) {                                              \
                int r = dir ? (clb[it] - 1 - (t)) * BB + cb[it]               \
                            : (t) * BB + cb[it];                             \
                gxp[it] = *(const uint2*)(gx + (size_t)r * 2048               \
                                              + (j0 + cjj[it]) * 4);          \
            }                                                                 \
        }                                                                     \
    }

    int na = g_nact[0];
    PREFETCH_GX(0)

    for (int t = 0; t < TT; t++) {
        const __half* hcur16 = g_h16[t & 1][dir];
        __half* hnext16 = g_h16[(t & 1) ^ 1][dir];
        const __half* hsrc = hcur16 + warp * 64;
        int mtmax = (na + 15) >> 4;
        bool upper = na > 32;

#pragma unroll
        for (int g = 0; g < 2; g++) {
#pragma unroll
            for (int i = 0; i < 8; i++) {
                if ((i & 1) && !upper) continue;    // rows 32..63 inactive
                int idx = (g * 8 + i) * 32 + lane;
                int r = idx & 63, c8 = idx >> 6;
                uint32_t byteoff = (uint32_t)(r * 128 + ((c8 ^ (r & 7)) << 4));
                cp_async16(myR_s + byteoff, hsrc + (size_t)r * HH + c8 * 8);
            }
            asm volatile("cp.async.commit_group;\n" ::: "memory");
        }

        float4 acc[4][4];
#pragma unroll
        for (int mt = 0; mt < 4; mt++)
#pragma unroll
            for (int nt = 0; nt < 4; nt++) acc[mt][nt] = make_float4(0.f, 0.f, 0.f, 0.f);

        asm volatile("cp.async.wait_group 1;\n" ::: "memory");
        __syncwarp();
#pragma unroll
        for (int kk = 0; kk < 2; kk++) {
            uint32_t a[4];
#pragma unroll
            for (int mt = 0; mt < 4; mt++) {
                if (mt >= mtmax) break;
                ldsm_x4(a[0], a[1], a[2], a[3],
                        mbase[mt] + (uint32_t)((((kk * 2 + hi) ^ m7[mt]) << 4)));
#pragma unroll
                for (int nt = 0; nt < 4; nt++) mma_f16(acc[mt][nt], a, wr[nt][kk]);
            }
        }
        asm volatile("cp.async.wait_group 0;\n" ::: "memory");
        __syncwarp();
#pragma unroll
        for (int kk = 2; kk < 4; kk++) {
            uint32_t a[4];
#pragma unroll
            for (int mt = 0; mt < 4; mt++) {
                if (mt >= mtmax) break;
                ldsm_x4(a[0], a[1], a[2], a[3],
                        mbase[mt] + (uint32_t)((((kk * 2 + hi) ^ m7[mt]) << 4)));
#pragma unroll
                for (int nt = 0; nt < 4; nt++) mma_f16(acc[mt][nt], a, wr[nt][kk]);
            }
        }
        __syncwarp();

#pragma unroll
        for (int mt = 0; mt < 4; mt++) {
            if (mt >= mtmax) break;
#pragma unroll
            for (int nt = 0; nt < 4; nt++) {
                int row = mt * 16 + gid, col = nt * 8 + tig * 2;
                *(float2*)&myR[row * 40 + col] = make_float2(acc[mt][nt].x, acc[mt][nt].y);
                *(float2*)&myR[(row + 8) * 40 + col] = make_float2(acc[mt][nt].z, acc[mt][nt].w);
            }
        }
        __syncthreads();

#pragma unroll
        for (int it = 0; it < 2; it++) {
            int b = cb[it], jj = cjj[it], lb = clb[it], bj = cbj[it];
            if (t < lb) {
                float gsum[4] = {0.f, 0.f, 0.f, 0.f};
#pragma unroll
                for (int w = 0; w < 8; w++) {
                    const float* pw = s + w * REGF + b * 40 + jj;
#pragma unroll
                    for (int q = 0; q < 4; q++) gsum[q] += pw[q * 8];
                }
                __half2* gp = reinterpret_cast<__half2*>(&gxp[it]);
                float2 fif = __half22float2(gp[0]);
                float2 fgo = __half22float2(gp[1]);
                float iv = gsum[0] + fif.x;
                float fv = gsum[1] + fif.y;
                float gv = gsum[2] + fgo.x;
                float ov = gsum[3] + fgo.y;
                float cn = sigm(fv) * creg[it] + sigm(iv) * tanhf(gv);
                float hn = sigm(ov) * tanhf(cn);
                creg[it] = cn;
                __half hh = __float2half_rn(hn);
                hnext16[bj] = hh;
                if (t == lb - 1) g_hout[dir][bj] = hn;
                int tout = dir ? (lb - 1 - t) : t;
                size_t xoff = (size_t)(tout * BB + b) * 1024 + dir * HH + j0 + jj;
                xo16[xoff] = hh;
                if (final) g_xf[xoff] = hn;
            } else if (t < lb + 2) {
                hnext16[bj] = hcur16[bj];
            }
        }

        __syncthreads();
        if (t < TT - 1) {
            unsigned* bar = &g_bar2[dir][0];
            if (tid == 0)
                asm volatile("red.release.gpu.global.add.u32 [%0], %1;"
                             :: "l"(bar), "r"(1u) : "memory");
            na = g_nact[t + 1];          // lands during spin
            PREFETCH_GX(t + 1)           // lands during spin
            if (tid == 0) {
                unsigned target = 64u * (unsigned)(t + 1), v;
                do {
                    asm volatile("ld.acquire.gpu.global.u32 %0, [%1];"
                                 : "=r"(v) : "l"(bar) : "memory");
                } while (v < target);
            }
            __syncthreads();
        }
    }

#pragma unroll
    for (int it = 0; it < 2; it++) g_c[dir][cbj[it]] = creg[it];
#undef PREFETCH_GX
}

extern "C" void kernel_launch(void* const* d_in, const int* in_sizes, int n_in,
                              void* d_out, int out_size) {
    const float* data   = (const float*)d_in[0];
    const float* h0     = (const float*)d_in[1];
    const float* c0     = (const float*)d_in[2];
    const float* w_ih0  = (const float*)d_in[3];
    const float* w_hh0  = (const float*)d_in[4];
    const float* b0     = (const float*)d_in[5];
    const float* w_ih_r = (const float*)d_in[6];
    const float* w_hh_r = (const float*)d_in[7];
    const float* b_r    = (const float*)d_in[8];
    const int*   pack   = (const int*)d_in[10];

    const int NP = in_sizes[0] / 512;
    float* out = (float*)d_out;

    static int smem_set = 0;
    if (!smem_set) {
        cudaFuncSetAttribute(k_scan, cudaFuncAttributeMaxDynamicSharedMemorySize, SCAN_SMEM);
        smem_set = 1;
    }

    k_len<<<1, 1024>>>(pack, NP);
    k_scatter<<<(NP * 512 + 255) / 256, 256>>>(data, pack, NP * 512);

    const int LX[3]  = {0, 1, 0};
    const int LLD[3] = {512, 1024, 1024};
    const int LK[3]  = {512, 1024, 1024};
    const int LO[3]  = {1, 0, 1};

    for (int l = 0; l < 3; l++) {
        const float* Wih = (l == 0) ? w_ih0 : w_ih_r + (size_t)(l - 1) * 2 * GG * 1024;
        int n4 = 2 * GG * LK[l] / 4;
        k_wcvt<<<(n4 + 255) / 256, 256>>>(Wih, n4);

        for (int d = 0; d < 2; d++) {
            const float* bs = (l == 0) ? b0 + (size_t)d * GG
                                       : b_r + (size_t)((l - 1) * 2 + d) * GG;
            k_gemm_gx<<<dim3(32, TB / 128), 256>>>(LX[l], LLD[l], LK[l], d, bs);
        }
        k_init<<<256, 256>>>(h0, c0, l);

        const float* W0 = (l == 0) ? w_hh0 : w_hh_r + (size_t)((l - 1) * 2 + 0) * GG * HH;
        const float* W1 = (l == 0) ? w_hh0 + (size_t)GG * HH
                                   : w_hh_r + (size_t)((l - 1) * 2 + 1) * GG * HH;
        k_scan<<<128, 256, SCAN_SMEM>>>(W0, W1, LO[l], l == 2);

        k_save<<<256, 256>>>(out, NP, l);
    }
    k_gather<<<(NP * 1024 + 255) / 256, 256>>>(out, pack, NP * 1024);
}

// round 17
// speedup vs baseline: 1.0100x; 1.0100x over previous
#include <cuda_runtime.h>
#include <cuda_fp16.h>
#include <cstdint>

#define TT 512
#define BB 64
#define HH 512
#define GG 2048
#define TB (TT*BB)

__device__ __align__(16) __half g_x16[2][(size_t)TB * 1024];   // layer activations (fp16)
__device__ __align__(16) float  g_xf[(size_t)TB * 1024];       // final-layer fp32 output
__device__ __align__(16) __half g_gx16[2][(size_t)TB * 2048];  // gate-interleaved [r][j][4]
__device__ __align__(16) __half g_w16[2 * 2048 * 1024];        // per-layer W_ih fp16
__device__ __align__(16) __half g_h16[2][2][BB * HH];
__device__ __align__(16) float  g_hout[2][BB * HH];
__device__ __align__(16) float  g_c[2][BB * HH];
__device__ int g_len[BB];
__device__ int g_nact[TT];
__device__ unsigned g_bar2[2][32];

__device__ __forceinline__ float sigm(float x) { return 1.0f / (1.0f + expf(-x)); }
__device__ __forceinline__ void cp_async16(uint32_t saddr, const void* gaddr) {
    asm volatile("cp.async.cg.shared.global [%0], [%1], 16;\n" :: "r"(saddr), "l"(gaddr));
}
__device__ __forceinline__ void ldsm_x4(uint32_t& r0, uint32_t& r1,
                                        uint32_t& r2, uint32_t& r3, uint32_t saddr) {
    asm volatile("ldmatrix.sync.aligned.m8n8.x4.shared.b16 {%0,%1,%2,%3}, [%4];"
                 : "=r"(r0), "=r"(r1), "=r"(r2), "=r"(r3) : "r"(saddr));
}
__device__ __forceinline__ void mma_f16(float4& d, const uint32_t* a, const uint32_t* b) {
    asm volatile(
        "mma.sync.aligned.m16n8k16.row.col.f32.f16.f16.f32 "
        "{%0,%1,%2,%3}, {%4,%5,%6,%7}, {%8,%9}, {%0,%1,%2,%3};\n"
        : "+f"(d.x), "+f"(d.y), "+f"(d.z), "+f"(d.w)
        : "r"(a[0]), "r"(a[1]), "r"(a[2]), "r"(a[3]), "r"(b[0]), "r"(b[1]));
}
__device__ __forceinline__ uint32_t h2u(__half2 h) { return *reinterpret_cast<uint32_t*>(&h); }

__global__ void k_len(const int* __restrict__ pack_idx, int NP) {
    __shared__ int cnt[BB];
    int tid = threadIdx.x;
    if (tid < BB) cnt[tid] = 0;
    __syncthreads();
    for (int i = tid; i < NP; i += blockDim.x)
        atomicAdd(&cnt[pack_idx[i] & (BB - 1)], 1);
    __syncthreads();
    if (tid < BB) g_len[tid] = cnt[tid];
    if (tid < TT) {
        int t = tid, na = 0;
#pragma unroll 8
        for (int b = 0; b < BB; b++) na += (cnt[b] > t) ? 1 : 0;
        g_nact[t] = na;
    }
}

__global__ void k_wcvt(const float* __restrict__ W, int n4) {
    int i = blockIdx.x * blockDim.x + threadIdx.x;
    if (i < n4) {
        float4 v = *(const float4*)(W + (size_t)i * 4);
        uint2 h = { h2u(__floats2half2_rn(v.x, v.y)), h2u(__floats2half2_rn(v.z, v.w)) };
        *(uint2*)(g_w16 + (size_t)i * 4) = h;
    }
}

__global__ void k_scatter(const float* __restrict__ data, const int* __restrict__ pack_idx, int total) {
    int e = blockIdx.x * blockDim.x + threadIdx.x;
    if (e < total) {
        int i = e >> 9, col = e & 511;
        g_x16[0][(size_t)pack_idx[i] * 512 + col] = __float2half_rn(data[e]);
    }
}

__global__ void k_gather(float* __restrict__ out, const int* __restrict__ pack_idx, int total) {
    int e = blockIdx.x * blockDim.x + threadIdx.x;
    if (e < total) {
        int i = e >> 10, col = e & 1023;
        out[e] = g_xf[(size_t)pack_idx[i] * 1024 + col];
    }
}

__global__ void k_init(const float* __restrict__ h0, const float* __restrict__ c0, int l) {
    int idx = blockIdx.x * blockDim.x + threadIdx.x;
    if (idx < 2) g_bar2[idx][0] = 0u;
    int dir = idx >> 15, rem = idx & 32767;
    size_t src = (size_t)(2 * l + dir) * 32768 + rem;
    float h = h0[src];
    g_h16[0][dir][rem] = __float2half_rn(h);
    g_hout[dir][rem]   = h;
    g_c[dir][rem]      = c0[src];
}

__global__ void k_save(float* __restrict__ out, int NP, int l) {
    int idx = blockIdx.x * blockDim.x + threadIdx.x;
    int dir = idx >> 15, rem = idx & 32767;
    size_t OH = (size_t)NP * 1024;
    size_t off = (size_t)(2 * l + dir) * 32768 + rem;
    out[OH + off]             = g_hout[dir][rem];
    out[OH + 6 * 32768 + off] = g_c[dir][rem];
}

// ---------------------------------------------------------------------------
// Input GEMM, cp.async 3-stage pipeline, all-fp16 operands.
// grid = (32 n-tiles, 256 m-tiles)  [n fast -> X reused 32x from L2]
// Writes gx gate-interleaved fp16: g_gx16[dir][row*2048 + j*4 + quad].
// ---------------------------------------------------------------------------
__global__ __launch_bounds__(256)
void k_gemm_gx(int xsel, int ldx, int K, int dir, const float* __restrict__ bias) {
    const __half* X = g_x16[xsel];
    const __half* W = g_w16 + (size_t)dir * 2048 * K;
    __half* og = g_gx16[dir];

    __shared__ __align__(16) __half Xs[3][128 * 40];
    __shared__ __align__(16) __half Wsm[3][64 * 40];
    uint32_t Xs_s = (uint32_t)__cvta_generic_to_shared(&Xs[0][0]);
    uint32_t Ws_s = (uint32_t)__cvta_generic_to_shared(&Wsm[0][0]);

    int tid = threadIdx.x, lane = tid & 31, warp = tid >> 5;
    int wm = warp & 3, wn = warp >> 2;
    int gid = lane >> 2, tig = lane & 3;
    int sel = lane >> 3, rowin = lane & 7;
    int n0 = blockIdx.x * 64, m0 = blockIdx.y * 128;
    int NC = K / 32;

    float4 acc[2][4];
#pragma unroll
    for (int mt = 0; mt < 2; mt++)
#pragma unroll
        for (int nt = 0; nt < 4; nt++) acc[mt][nt] = make_float4(0.f, 0.f, 0.f, 0.f);

#define GPREF(kc, st)                                                          \
    {                                                                          \
        int k0 = (kc) * 32;                                                    \
        uint32_t xb = Xs_s + (uint32_t)(st) * 10240;                           \
        _Pragma("unroll")                                                      \
        for (int i = 0; i < 2; i++) {                                          \
            int idx = i * 256 + tid, r = idx >> 2, c = idx & 3;                \
            cp_async16(xb + (uint32_t)(r * 80 + c * 16),                       \
                       X + (size_t)(m0 + r) * ldx + k0 + c * 8);               \
        }                                                                      \
        uint32_t wb = Ws_s + (uint32_t)(st) * 5120;                            \
        { int r = tid >> 2, c = tid & 3;                                       \
          cp_async16(wb + (uint32_t)(r * 80 + c * 16),                         \
                     W + (size_t)(n0 + r) * K + k0 + c * 8); }                 \
        asm volatile("cp.async.commit_group;\n" ::: "memory");                 \
    }

    GPREF(0, 0)
    GPREF(1, 1)

    for (int kc = 0; kc < NC; kc++) {
        asm volatile("cp.async.wait_group 1;\n" ::: "memory");
        __syncthreads();
        if (kc + 2 < NC) GPREF(kc + 2, (kc + 2) % 3)
        uint32_t xb = Xs_s + (uint32_t)(kc % 3) * 10240;
        uint32_t wb = Ws_s + (uint32_t)(kc % 3) * 5120;
#pragma unroll
        for (int kk = 0; kk < 2; kk++) {
            uint32_t a[2][4], b[4][2];
#pragma unroll
            for (int mt = 0; mt < 2; mt++) {
                int m = wm * 32 + mt * 16 + (sel & 1) * 8 + rowin;
                int c8 = kk * 2 + (sel >> 1);
                ldsm_x4(a[mt][0], a[mt][1], a[mt][2], a[mt][3],
                        xb + (uint32_t)(m * 80 + c8 * 16));
            }
#pragma unroll
            for (int p = 0; p < 2; p++) {
                int quad = lane >> 3;
                int n = wn * 32 + p * 16 + (quad >> 1) * 8 + rowin;
                int c8 = kk * 2 + (quad & 1);
                ldsm_x4(b[p * 2][0], b[p * 2][1], b[p * 2 + 1][0], b[p * 2 + 1][1],
                        wb + (uint32_t)(n * 80 + c8 * 16));
            }
#pragma unroll
            for (int mt = 0; mt < 2; mt++)
#pragma unroll
                for (int nt = 0; nt < 4; nt++) mma_f16(acc[mt][nt], a[mt], b[nt]);
        }
    }
#undef GPREF

#pragma unroll
    for (int mt = 0; mt < 2; mt++)
#pragma unroll
        for (int nt = 0; nt < 4; nt++) {
            int row = m0 + wm * 32 + mt * 16 + gid;
            int col = n0 + wn * 32 + nt * 8 + tig * 2;
            int quad = col >> 9, j = col & 511;
            float bx = bias[col], by = bias[col + 1];
            size_t base = (size_t)row * 2048 + j * 4 + quad;
            og[base]     = __float2half_rn(acc[mt][nt].x + bx);
            og[base + 4] = __float2half_rn(acc[mt][nt].y + by);
            base += (size_t)8 * 2048;
            og[base]     = __float2half_rn(acc[mt][nt].z + bx);
            og[base + 4] = __float2half_rn(acc[mt][nt].w + by);
        }
}

// ---------------------------------------------------------------------------
// Persistent scan (fp16 split-K). Changes vs R13: gx16 interleaved prefetch
// moved AFTER barrier arrive; active-tile bounding via g_nact.
// ---------------------------------------------------------------------------
#define REGF 2560
#define SCAN_SMEM (8 * REGF * 4)

__global__ __launch_bounds__(256, 1)
void k_scan(const float* __restrict__ Whh0, const float* __restrict__ Whh1,
            int xoutsel, int final) {
    extern __shared__ float s[];
    int bid = blockIdx.x;
    int dir = bid >> 6;
    int j0 = (bid & 63) * 8;
    const float* Whh = dir ? Whh1 : Whh0;
    const __half* gx = g_gx16[dir];
    __half* xo16 = g_x16[xoutsel];

    int tid = threadIdx.x, lane = tid & 31, warp = tid >> 5;
    int gid = lane >> 2, tig = lane & 3;
    int sel = lane >> 3, rowin = lane & 7;
    float* myR = s + warp * REGF;
    uint32_t myR_s = (uint32_t)__cvta_generic_to_shared(myR);

    int hi = sel >> 1;
    uint32_t mbase[4];
    int m7[4];
#pragma unroll
    for (int mt = 0; mt < 4; mt++) {
        int m = mt * 16 + (sel & 1) * 8 + rowin;
        mbase[mt] = myR_s + (uint32_t)(m * 128);
        m7[mt] = m & 7;
    }

    uint32_t wr[4][4][2];
#pragma unroll
    for (int nt = 0; nt < 4; nt++) {
        const float* wrow = Whh + (size_t)(nt * 512 + j0 + gid) * HH + warp * 64;
#pragma unroll
        for (int kk = 0; kk < 4; kk++) {
            const float* wp = wrow + kk * 16;
            wr[nt][kk][0] = h2u(__floats2half2_rn(__ldg(wp + 2 * tig), __ldg(wp + 2 * tig + 1)));
            wr[nt][kk][1] = h2u(__floats2half2_rn(__ldg(wp + 2 * tig + 8), __ldg(wp + 2 * tig + 9)));
        }
    }

    int cb[2], cjj[2], clb[2], cbj[2];
    float creg[2];
    uint2 gxp[2];
#pragma unroll
    for (int it = 0; it < 2; it++) {
        int cell = it * 256 + tid;
        cb[it] = cell >> 3; cjj[it] = cell & 7;
        clb[it] = g_len[cb[it]];
        cbj[it] = cb[it] * HH + j0 + cjj[it];
        creg[it] = g_c[dir][cbj[it]];
    }

#define PREFETCH_GX(t)                                                        \
    {                                                                         \
        _Pragma("unroll")                                                     \
        for (int it = 0; it < 2; it++) {                                      \
            if ((t) < clb[it]) {                                              \
                int r = dir ? (clb[it] - 1 - (t)) * BB + cb[it]               \
                            : (t) * BB + cb[it];                             \
                gxp[it] = *(const uint2*)(gx + (size_t)r * 2048               \
                                              + (j0 + cjj[it]) * 4);          \
            }                                                                 \
        }                                                                     \
    }

    int na = g_nact[0];
    PREFETCH_GX(0)

    for (int t = 0; t < TT; t++) {
        const __half* hcur16 = g_h16[t & 1][dir];
        __half* hnext16 = g_h16[(t & 1) ^ 1][dir];
        const __half* hsrc = hcur16 + warp * 64;
        int mtmax = (na + 15) >> 4;
        bool upper = na > 32;

#pragma unroll
        for (int g = 0; g < 2; g++) {
#pragma unroll
            for (int i = 0; i < 8; i++) {
                if ((i & 1) && !upper) continue;    // rows 32..63 inactive
                int idx = (g * 8 + i) * 32 + lane;
                int r = idx & 63, c8 = idx >> 6;
                uint32_t byteoff = (uint32_t)(r * 128 + ((c8 ^ (r & 7)) << 4));
                cp_async16(myR_s + byteoff, hsrc + (size_t)r * HH + c8 * 8);
            }
            asm volatile("cp.async.commit_group;\n" ::: "memory");
        }

        float4 acc[4][4];
#pragma unroll
        for (int mt = 0; mt < 4; mt++)
#pragma unroll
            for (int nt = 0; nt < 4; nt++) acc[mt][nt] = make_float4(0.f, 0.f, 0.f, 0.f);

        asm volatile("cp.async.wait_group 1;\n" ::: "memory");
        __syncwarp();
#pragma unroll
        for (int kk = 0; kk < 2; kk++) {
            uint32_t a[4];
#pragma unroll
            for (int mt = 0; mt < 4; mt++) {
                if (mt >= mtmax) break;
                ldsm_x4(a[0], a[1], a[2], a[3],
                        mbase[mt] + (uint32_t)((((kk * 2 + hi) ^ m7[mt]) << 4)));
#pragma unroll
                for (int nt = 0; nt < 4; nt++) mma_f16(acc[mt][nt], a, wr[nt][kk]);
            }
        }
        asm volatile("cp.async.wait_group 0;\n" ::: "memory");
        __syncwarp();
#pragma unroll
        for (int kk = 2; kk < 4; kk++) {
            uint32_t a[4];
#pragma unroll
            for (int mt = 0; mt < 4; mt++) {
                if (mt >= mtmax) break;
                ldsm_x4(a[0], a[1], a[2], a[3],
                        mbase[mt] + (uint32_t)((((kk * 2 + hi) ^ m7[mt]) << 4)));
#pragma unroll
                for (int nt = 0; nt < 4; nt++) mma_f16(acc[mt][nt], a, wr[nt][kk]);
            }
        }
        __syncwarp();

#pragma unroll
        for (int mt = 0; mt < 4; mt++) {
            if (mt >= mtmax) break;
#pragma unroll
            for (int nt = 0; nt < 4; nt++) {
                int row = mt * 16 + gid, col = nt * 8 + tig * 2;
                *(float2*)&myR[row * 40 + col] = make_float2(acc[mt][nt].x, acc[mt][nt].y);
                *(float2*)&myR[(row + 8) * 40 + col] = make_float2(acc[mt][nt].z, acc[mt][nt].w);
            }
        }
        __syncthreads();

#pragma unroll
        for (int it = 0; it < 2; it++) {
            int b = cb[it], jj = cjj[it], lb = clb[it], bj = cbj[it];
            if (t < lb) {
                float gsum[4] = {0.f, 0.f, 0.f, 0.f};
#pragma unroll
                for (int w = 0; w < 8; w++) {
                    const float* pw = s + w * REGF + b * 40 + jj;
#pragma unroll
                    for (int q = 0; q < 4; q++) gsum[q] += pw[q * 8];
                }
                __half2* gp = reinterpret_cast<__half2*>(&gxp[it]);
                float2 fif = __half22float2(gp[0]);
                float2 fgo = __half22float2(gp[1]);
                float iv = gsum[0] + fif.x;
                float fv = gsum[1] + fif.y;
                float gv = gsum[2] + fgo.x;
                float ov = gsum[3] + fgo.y;
                float cn = sigm(fv) * creg[it] + sigm(iv) * tanhf(gv);
                float hn = sigm(ov) * tanhf(cn);
                creg[it] = cn;
                __half hh = __float2half_rn(hn);
                hnext16[bj] = hh;
                if (t == lb - 1) g_hout[dir][bj] = hn;
                int tout = dir ? (lb - 1 - t) : t;
                size_t xoff = (size_t)(tout * BB + b) * 1024 + dir * HH + j0 + jj;
                xo16[xoff] = hh;
                if (final) g_xf[xoff] = hn;
            } else if (t < lb + 2) {
                hnext16[bj] = hcur16[bj];
            }
        }

        __syncthreads();
        if (t < TT - 1) {
            unsigned* bar = &g_bar2[dir][0];
            if (tid == 0)
                asm volatile("red.release.gpu.global.add.u32 [%0], %1;"
                             :: "l"(bar), "r"(1u) : "memory");
            na = g_nact[t + 1];          // lands during spin
            PREFETCH_GX(t + 1)           // lands during spin
            if (tid == 0) {
                unsigned target = 64u * (unsigned)(t + 1), v;
                do {
                    asm volatile("ld.acquire.gpu.global.u32 %0, [%1];"
                                 : "=r"(v) : "l"(bar) : "memory");
                } while (v < target);
            }
            __syncthreads();
        }
    }

#pragma unroll
    for (int it = 0; it < 2; it++) g_c[dir][cbj[it]] = creg[it];
#undef PREFETCH_GX
}

extern "C" void kernel_launch(void* const* d_in, const int* in_sizes, int n_in,
                              void* d_out, int out_size) {
    const float* data   = (const float*)d_in[0];
    const float* h0     = (const float*)d_in[1];
    const float* c0     = (const float*)d_in[2];
    const float* w_ih0  = (const float*)d_in[3];
    const float* w_hh0  = (const float*)d_in[4];
    const float* b0     = (const float*)d_in[5];
    const float* w_ih_r = (const float*)d_in[6];
    const float* w_hh_r = (const float*)d_in[7];
    const float* b_r    = (const float*)d_in[8];
    const int*   pack   = (const int*)d_in[10];

    const int NP = in_sizes[0] / 512;
    float* out = (float*)d_out;

    static int smem_set = 0;
    if (!smem_set) {
        cudaFuncSetAttribute(k_scan, cudaFuncAttributeMaxDynamicSharedMemorySize, SCAN_SMEM);
        smem_set = 1;
    }

    k_len<<<1, 1024>>>(pack, NP);
    k_scatter<<<(NP * 512 + 255) / 256, 256>>>(data, pack, NP * 512);

    const int LX[3]  = {0, 1, 0};
    const int LLD[3] = {512, 1024, 1024};
    const int LK[3]  = {512, 1024, 1024};
    const int LO[3]  = {1, 0, 1};

    for (int l = 0; l < 3; l++) {
        const float* Wih = (l == 0) ? w_ih0 : w_ih_r + (size_t)(l - 1) * 2 * GG * 1024;
        int n4 = 2 * GG * LK[l] / 4;
        k_wcvt<<<(n4 + 255) / 256, 256>>>(Wih, n4);

        for (int d = 0; d < 2; d++) {
            const float* bs = (l == 0) ? b0 + (size_t)d * GG
                                       : b_r + (size_t)((l - 1) * 2 + d) * GG;
            k_gemm_gx<<<dim3(32, TB / 128), 256>>>(LX[l], LLD[l], LK[l], d, bs);
        }
        k_init<<<256, 256>>>(h0, c0, l);

        const float* W0 = (l == 0) ? w_hh0 : w_hh_r + (size_t)((l - 1) * 2 + 0) * GG * HH;
        const float* W1 = (l == 0) ? w_hh0 + (size_t)GG * HH
                                   : w_hh_r + (size_t)((l - 1) * 2 + 1) * GG * HH;
        k_scan<<<128, 256, SCAN_SMEM>>>(W0, W1, LO[l], l == 2);

        k_save<<<256, 256>>>(out, NP, l);
    }
    k_gather<<<(NP * 1024 + 255) / 256, 256>>>(out, pack, NP * 1024);
}